// round 3
// baseline (speedup 1.0000x reference)
#include <cuda_runtime.h>
#include <cstdint>
#include <cstddef>

#define NN   50000
#define EE   800000
#define DIN  128
#define DH   256

// ---------------- scratch (device globals; no allocation allowed) ------------
__device__ float g_dinv[NN];            // deg -> dinv in place
__device__ float g_agg1[NN * DIN];      // A @ x
__device__ float g_h[(size_t)NN * DH];  // relu(agg1 @ W1^T + b1)
__device__ float g_p[NN * DIN];         // h @ W2^T (no bias)
__device__ float g_agg2[NN * DIN];      // A @ p
__device__ int   g_src[EE];             // clean int32 src ids
__device__ int   g_dst[EE];             // clean int32 dst ids
__device__ int   g_is64;                // 1 if edge_index buffer is int64

// ---------------- dtype sniffer ----------------------------------------------
// int64 little-endian: odd int32 words are high halves of ids < 50000 -> zero.
__global__ void detect_idx_kernel(const int* __restrict__ raw) {
    __shared__ int nz;
    if (threadIdx.x == 0) nz = 0;
    __syncthreads();
    if (raw[2 * threadIdx.x + 1] != 0) atomicOr(&nz, 1);
    __syncthreads();
    if (threadIdx.x == 0) g_is64 = (nz == 0) ? 1 : 0;
}

// ---------------- convert indices + accumulate weighted in-degree ------------
// deg must be zeroed beforehand (cudaMemsetAsync). Self-loop +1 folded into
// dinv_kernel.
__global__ void convert_deg_kernel(const void* __restrict__ raw,
                                   const float* __restrict__ w,
                                   int* __restrict__ src,
                                   int* __restrict__ dst,
                                   float* __restrict__ deg, int e) {
    int i = blockIdx.x * blockDim.x + threadIdx.x;
    if (i >= e) return;
    int s, d;
    if (g_is64) {
        const long long* p = (const long long*)raw;
        s = (int)p[i];
        d = (int)p[(size_t)e + i];
    } else {
        const int* p = (const int*)raw;
        s = p[i];
        d = p[e + i];
    }
    src[i] = s;
    dst[i] = d;
    atomicAdd(&deg[d], w[i]);
}

__global__ void dinv_kernel(float* deg, int n) {
    int i = blockIdx.x * blockDim.x + threadIdx.x;
    if (i < n) deg[i] = rsqrtf(deg[i] + 1.0f);   // +1 = self-loop weight
}

// ---------------- self-loop init (doubles as zero-init of agg) ---------------
__global__ void selfloop_init_kernel(const float* __restrict__ feat,
                                     const float* __restrict__ dinv,
                                     float* __restrict__ agg, int total) {
    int i = blockIdx.x * blockDim.x + threadIdx.x;
    if (i < total) {
        int node = i >> 7;   // DIN = 128
        float dv = dinv[node];
        agg[i] = feat[i] * dv * dv;
    }
}

// ---------------- edge scatter: one warp per edge, 128-wide ------------------
__global__ void edge_scatter_kernel(const int* __restrict__ srcA,
                                    const int* __restrict__ dstA,
                                    const float* __restrict__ w,
                                    const float* __restrict__ dinv,
                                    const float* __restrict__ feat,
                                    float* __restrict__ agg, int e) {
    int gw   = (blockIdx.x * blockDim.x + threadIdx.x) >> 5;
    int lane = threadIdx.x & 31;
    if (gw >= e) return;

    int s = srcA[gw];
    int d = dstA[gw];
    float nrm = dinv[s] * w[gw] * dinv[d];

    float4 v = *(const float4*)(feat + (size_t)s * DIN + lane * 4);
    float* out = agg + (size_t)d * DIN + lane * 4;
    asm volatile("red.global.add.v4.f32 [%0], {%1, %2, %3, %4};"
                 :: "l"(out), "f"(v.x * nrm), "f"(v.y * nrm),
                    "f"(v.z * nrm), "f"(v.w * nrm)
                 : "memory");
}

// ---------------- fp32 GEMM: C[m][n] = sum_k A[m][k] * W[n][k] ---------------
// BM=128 BN=128 BK=16, 256 threads, TM=TN=8, double-buffered k-major smem.
// A: [M,K] row-major. W: [Nout,K] row-major. K % 16 == 0, Nout % 128 == 0.
__global__ __launch_bounds__(256)
void gemm_tn_kernel(const float* __restrict__ A, const float* __restrict__ W,
                    const float* __restrict__ bias, float* __restrict__ C,
                    int M, int K, int Nout, int doRelu) {
    constexpr int BM = 128, BN = 128, BK = 16;
    __shared__ float As[2][BK][BM];
    __shared__ float Ws[2][BK][BN];

    const int tid = threadIdx.x;
    const int tx  = tid & 15;   // 16 col groups  (n = n0 + tx*8 ..)
    const int ty  = tid >> 4;   // 16 row groups  (m = m0 + ty*8 ..)
    const int m0  = blockIdx.x * BM;
    const int n0  = blockIdx.y * BN;

    // per-thread load coords: two (row, kq) pairs, rows 0..127, kq 0..3
    const int r0 = tid & 127, q0 = tid >> 7;          // kq 0..1
    const int r1 = r0,        q1 = q0 + 2;            // kq 2..3

    float acc[8][8];
#pragma unroll
    for (int i = 0; i < 8; i++)
#pragma unroll
        for (int j = 0; j < 8; j++) acc[i][j] = 0.f;

    const int nt = K / BK;

    float4 la0, la1, lw0, lw1;
    // prefetch tile 0
    {
        la0 = (m0 + r0 < M) ? *(const float4*)(A + (size_t)(m0 + r0) * K + q0 * 4)
                            : make_float4(0.f, 0.f, 0.f, 0.f);
        la1 = (m0 + r1 < M) ? *(const float4*)(A + (size_t)(m0 + r1) * K + q1 * 4)
                            : make_float4(0.f, 0.f, 0.f, 0.f);
        lw0 = *(const float4*)(W + (size_t)(n0 + r0) * K + q0 * 4);
        lw1 = *(const float4*)(W + (size_t)(n0 + r1) * K + q1 * 4);
        As[0][q0 * 4 + 0][r0] = la0.x; As[0][q0 * 4 + 1][r0] = la0.y;
        As[0][q0 * 4 + 2][r0] = la0.z; As[0][q0 * 4 + 3][r0] = la0.w;
        As[0][q1 * 4 + 0][r1] = la1.x; As[0][q1 * 4 + 1][r1] = la1.y;
        As[0][q1 * 4 + 2][r1] = la1.z; As[0][q1 * 4 + 3][r1] = la1.w;
        Ws[0][q0 * 4 + 0][r0] = lw0.x; Ws[0][q0 * 4 + 1][r0] = lw0.y;
        Ws[0][q0 * 4 + 2][r0] = lw0.z; Ws[0][q0 * 4 + 3][r0] = lw0.w;
        Ws[0][q1 * 4 + 0][r1] = lw1.x; Ws[0][q1 * 4 + 1][r1] = lw1.y;
        Ws[0][q1 * 4 + 2][r1] = lw1.z; Ws[0][q1 * 4 + 3][r1] = lw1.w;
    }
    __syncthreads();

    for (int t = 0; t < nt; t++) {
        const int buf = t & 1;
        // prefetch next tile into registers
        if (t + 1 < nt) {
            const int k0 = (t + 1) * BK;
            la0 = (m0 + r0 < M) ? *(const float4*)(A + (size_t)(m0 + r0) * K + k0 + q0 * 4)
                                : make_float4(0.f, 0.f, 0.f, 0.f);
            la1 = (m0 + r1 < M) ? *(const float4*)(A + (size_t)(m0 + r1) * K + k0 + q1 * 4)
                                : make_float4(0.f, 0.f, 0.f, 0.f);
            lw0 = *(const float4*)(W + (size_t)(n0 + r0) * K + k0 + q0 * 4);
            lw1 = *(const float4*)(W + (size_t)(n0 + r1) * K + k0 + q1 * 4);
        }

        // compute on current buffer
#pragma unroll
        for (int k = 0; k < BK; k++) {
            float4 a0 = *(const float4*)&As[buf][k][ty * 8];
            float4 a1 = *(const float4*)&As[buf][k][ty * 8 + 4];
            float4 b0 = *(const float4*)&Ws[buf][k][tx * 8];
            float4 b1 = *(const float4*)&Ws[buf][k][tx * 8 + 4];
            float av[8] = {a0.x, a0.y, a0.z, a0.w, a1.x, a1.y, a1.z, a1.w};
            float bv[8] = {b0.x, b0.y, b0.z, b0.w, b1.x, b1.y, b1.z, b1.w};
#pragma unroll
            for (int i = 0; i < 8; i++)
#pragma unroll
                for (int j = 0; j < 8; j++)
                    acc[i][j] = fmaf(av[i], bv[j], acc[i][j]);
        }

        // store prefetched tile into other buffer
        if (t + 1 < nt) {
            const int nb = buf ^ 1;
            As[nb][q0 * 4 + 0][r0] = la0.x; As[nb][q0 * 4 + 1][r0] = la0.y;
            As[nb][q0 * 4 + 2][r0] = la0.z; As[nb][q0 * 4 + 3][r0] = la0.w;
            As[nb][q1 * 4 + 0][r1] = la1.x; As[nb][q1 * 4 + 1][r1] = la1.y;
            As[nb][q1 * 4 + 2][r1] = la1.z; As[nb][q1 * 4 + 3][r1] = la1.w;
            Ws[nb][q0 * 4 + 0][r0] = lw0.x; Ws[nb][q0 * 4 + 1][r0] = lw0.y;
            Ws[nb][q0 * 4 + 2][r0] = lw0.z; Ws[nb][q0 * 4 + 3][r0] = lw0.w;
            Ws[nb][q1 * 4 + 0][r1] = lw1.x; Ws[nb][q1 * 4 + 1][r1] = lw1.y;
            Ws[nb][q1 * 4 + 2][r1] = lw1.z; Ws[nb][q1 * 4 + 3][r1] = lw1.w;
            __syncthreads();
        }
    }

    // epilogue
    const int col0 = n0 + tx * 8;
    float4 bb0 = make_float4(0.f, 0.f, 0.f, 0.f), bb1 = bb0;
    if (bias) {
        bb0 = *(const float4*)(bias + col0);
        bb1 = *(const float4*)(bias + col0 + 4);
    }
#pragma unroll
    for (int i = 0; i < 8; i++) {
        int row = m0 + ty * 8 + i;
        if (row >= M) break;
        float4 v0 = make_float4(acc[i][0] + bb0.x, acc[i][1] + bb0.y,
                                acc[i][2] + bb0.z, acc[i][3] + bb0.w);
        float4 v1 = make_float4(acc[i][4] + bb1.x, acc[i][5] + bb1.y,
                                acc[i][6] + bb1.z, acc[i][7] + bb1.w);
        if (doRelu) {
            v0.x = fmaxf(v0.x, 0.f); v0.y = fmaxf(v0.y, 0.f);
            v0.z = fmaxf(v0.z, 0.f); v0.w = fmaxf(v0.w, 0.f);
            v1.x = fmaxf(v1.x, 0.f); v1.y = fmaxf(v1.y, 0.f);
            v1.z = fmaxf(v1.z, 0.f); v1.w = fmaxf(v1.w, 0.f);
        }
        *(float4*)(C + (size_t)row * Nout + col0)     = v0;
        *(float4*)(C + (size_t)row * Nout + col0 + 4) = v1;
    }
}

// ---------------- LayerNorm (+ bias b2): one warp per row --------------------
__global__ void ln_kernel(const float* __restrict__ agg2,
                          const float* __restrict__ b2,
                          const float* __restrict__ gamma,
                          const float* __restrict__ beta,
                          float* __restrict__ out, int n) {
    int row  = (blockIdx.x * blockDim.x + threadIdx.x) >> 5;
    int lane = threadIdx.x & 31;
    if (row >= n) return;

    float4 v  = *(const float4*)(agg2 + (size_t)row * DIN + lane * 4);
    float4 bb = *(const float4*)(b2 + lane * 4);
    v.x += bb.x; v.y += bb.y; v.z += bb.z; v.w += bb.w;

    float s = v.x + v.y + v.z + v.w;
#pragma unroll
    for (int o = 16; o > 0; o >>= 1) s += __shfl_xor_sync(0xFFFFFFFFu, s, o);
    float mu = s * (1.0f / DIN);

    float dx = v.x - mu, dy = v.y - mu, dz = v.z - mu, dw = v.w - mu;
    float q = dx * dx + dy * dy + dz * dz + dw * dw;
#pragma unroll
    for (int o = 16; o > 0; o >>= 1) q += __shfl_xor_sync(0xFFFFFFFFu, q, o);
    float rstd = rsqrtf(q * (1.0f / DIN) + 1e-5f);

    float4 g  = *(const float4*)(gamma + lane * 4);
    float4 bt = *(const float4*)(beta + lane * 4);
    float4 o4;
    o4.x = dx * rstd * g.x + bt.x;
    o4.y = dy * rstd * g.y + bt.y;
    o4.z = dz * rstd * g.z + bt.z;
    o4.w = dw * rstd * g.w + bt.w;
    *(float4*)(out + (size_t)row * DIN + lane * 4) = o4;
}

// -----------------------------------------------------------------------------
extern "C" void kernel_launch(void* const* d_in, const int* in_sizes, int n_in,
                              void* d_out, int out_size) {
    const float* x     = (const float*)d_in[0];
    const void*  ei    = d_in[1];                 // int32 or int64, sniffed
    const float* ew    = (const float*)d_in[2];
    const float* W1    = (const float*)d_in[3];
    const float* b1    = (const float*)d_in[4];
    const float* W2    = (const float*)d_in[5];
    const float* b2    = (const float*)d_in[6];
    const float* gamma = (const float*)d_in[7];
    const float* beta  = (const float*)d_in[8];
    float*       out   = (float*)d_out;

    float *dinv, *agg1, *h, *p, *agg2;
    int *src, *dst;
    cudaGetSymbolAddress((void**)&dinv, g_dinv);
    cudaGetSymbolAddress((void**)&agg1, g_agg1);
    cudaGetSymbolAddress((void**)&h,    g_h);
    cudaGetSymbolAddress((void**)&p,    g_p);
    cudaGetSymbolAddress((void**)&agg2, g_agg2);
    cudaGetSymbolAddress((void**)&src,  g_src);
    cudaGetSymbolAddress((void**)&dst,  g_dst);

    const int n = NN, e = EE;

    // 0. sniff dtype; zero degree buffer
    detect_idx_kernel<<<1, 128>>>((const int*)ei);
    cudaMemsetAsync(dinv, 0, n * sizeof(float));

    // 1. convert indices + accumulate weighted in-degree (fused)
    convert_deg_kernel<<<(e + 255) / 256, 256>>>(ei, ew, src, dst, dinv, e);
    dinv_kernel<<<(n + 255) / 256, 256>>>(dinv, n);

    // 2. agg1 = A_norm @ x  (self-loop pass doubles as zero-init)
    selfloop_init_kernel<<<(n * DIN + 255) / 256, 256>>>(x, dinv, agg1, n * DIN);
    edge_scatter_kernel<<<(e * 32 + 255) / 256, 256>>>(src, dst, ew, dinv, x, agg1, e);

    // 3. h = relu(agg1 @ W1^T + b1)   [N x 256]
    {
        dim3 grid((n + 127) / 128, DH / 128);
        gemm_tn_kernel<<<grid, 256>>>(agg1, W1, b1, h, n, DIN, DH, 1);
    }

    // 4. p = h @ W2^T  [N x 128], bias deferred to LN
    {
        dim3 grid((n + 127) / 128, DIN / 128);
        gemm_tn_kernel<<<grid, 256>>>(h, W2, nullptr, p, n, DH, DIN, 0);
    }

    // 5. agg2 = A_norm @ p
    selfloop_init_kernel<<<(n * DIN + 255) / 256, 256>>>(p, dinv, agg2, n * DIN);
    edge_scatter_kernel<<<(e * 32 + 255) / 256, 256>>>(src, dst, ew, dinv, p, agg2, e);

    // 6. out = LN(agg2 + b2) * gamma + beta
    ln_kernel<<<(n * 32 + 255) / 256, 256>>>(agg2, b2, gamma, beta, out, n);
}

// round 4
// speedup vs baseline: 1.4080x; 1.4080x over previous
#include <cuda_runtime.h>
#include <cstdint>
#include <cstddef>

#define NN   50000
#define EE   800000
#define DIN  128
#define DH   256

// ---------------- scratch (device globals; no allocation allowed) ------------
__device__ float g_dinv[NN];            // deg -> dinv in place
__device__ float g_agg1[NN * DIN];      // A @ x
__device__ float g_h[(size_t)NN * DH];  // relu(agg1 @ W1^T + b1)
__device__ float g_p[NN * DIN];         // h @ W2^T (no bias)
__device__ float g_agg2[NN * DIN];      // A @ p
__device__ int   g_src[EE];             // clean int32 src ids
__device__ int   g_dst[EE];             // clean int32 dst ids
__device__ int   g_is64;                // 1 if edge_index buffer is int64

// ---------------- dtype sniffer ----------------------------------------------
__global__ void detect_idx_kernel(const int* __restrict__ raw) {
    __shared__ int nz;
    if (threadIdx.x == 0) nz = 0;
    __syncthreads();
    if (raw[2 * threadIdx.x + 1] != 0) atomicOr(&nz, 1);
    __syncthreads();
    if (threadIdx.x == 0) g_is64 = (nz == 0) ? 1 : 0;
}

// ---------------- convert indices + accumulate weighted in-degree ------------
__global__ void convert_deg_kernel(const void* __restrict__ raw,
                                   const float* __restrict__ w,
                                   int* __restrict__ src,
                                   int* __restrict__ dst,
                                   float* __restrict__ deg, int e) {
    int i = blockIdx.x * blockDim.x + threadIdx.x;
    if (i >= e) return;
    int s, d;
    if (g_is64) {
        const long long* p = (const long long*)raw;
        s = (int)p[i];
        d = (int)p[(size_t)e + i];
    } else {
        const int* p = (const int*)raw;
        s = p[i];
        d = p[e + i];
    }
    src[i] = s;
    dst[i] = d;
    atomicAdd(&deg[d], w[i]);
}

__global__ void dinv_kernel(float* deg, int n) {
    int i = blockIdx.x * blockDim.x + threadIdx.x;
    if (i < n) deg[i] = rsqrtf(deg[i] + 1.0f);   // +1 = self-loop weight
}

// ---------------- self-loop init (doubles as zero-init of agg) ---------------
__global__ void selfloop_init_kernel(const float* __restrict__ feat,
                                     const float* __restrict__ dinv,
                                     float* __restrict__ agg, int total) {
    int i = blockIdx.x * blockDim.x + threadIdx.x;
    if (i < total) {
        int node = i >> 7;   // DIN = 128
        float dv = dinv[node];
        agg[i] = feat[i] * dv * dv;
    }
}

// ---------------- edge scatter: one warp per edge, 128-wide ------------------
__global__ void edge_scatter_kernel(const int* __restrict__ srcA,
                                    const int* __restrict__ dstA,
                                    const float* __restrict__ w,
                                    const float* __restrict__ dinv,
                                    const float* __restrict__ feat,
                                    float* __restrict__ agg, int e) {
    int gw   = (blockIdx.x * blockDim.x + threadIdx.x) >> 5;
    int lane = threadIdx.x & 31;
    if (gw >= e) return;

    int s = srcA[gw];
    int d = dstA[gw];
    float nrm = dinv[s] * w[gw] * dinv[d];

    float4 v = *(const float4*)(feat + (size_t)s * DIN + lane * 4);
    float* out = agg + (size_t)d * DIN + lane * 4;
    asm volatile("red.global.add.v4.f32 [%0], {%1, %2, %3, %4};"
                 :: "l"(out), "f"(v.x * nrm), "f"(v.y * nrm),
                    "f"(v.z * nrm), "f"(v.w * nrm)
                 : "memory");
}

// ---------------- TF32 tensor-core GEMM --------------------------------------
// C[m][n] = sum_k A[m][k] * W[n][k]  (+bias, optional relu)
// A: [M,K] row-major, W: [Nout,K] row-major. K % 32 == 0, Nout % 128 == 0.
// Block 128x128, 256 threads (8 warps, 4x2), warp tile 32x64 = 2x8 m16n8k8.

__device__ __forceinline__ uint32_t f2tf32(float f) {
    uint32_t u;
    asm("cvt.rna.tf32.f32 %0, %1;" : "=r"(u) : "f"(f));
    return u;
}

__device__ __forceinline__ void mma_tf32(float c[4], const uint32_t a[4],
                                         const uint32_t b[2]) {
    asm volatile(
        "mma.sync.aligned.m16n8k8.row.col.f32.tf32.tf32.f32 "
        "{%0,%1,%2,%3}, {%4,%5,%6,%7}, {%8,%9}, {%0,%1,%2,%3};"
        : "+f"(c[0]), "+f"(c[1]), "+f"(c[2]), "+f"(c[3])
        : "r"(a[0]), "r"(a[1]), "r"(a[2]), "r"(a[3]), "r"(b[0]), "r"(b[1]));
}

#define LDPAD 36   // floats per smem row (32 + 4): conflict-free frags, 16B aligned

__global__ __launch_bounds__(256)
void gemm_tf32_kernel(const float* __restrict__ A, const float* __restrict__ W,
                      const float* __restrict__ bias, float* __restrict__ C,
                      int M, int K, int Nout, int doRelu) {
    __shared__ uint32_t As[128 * LDPAD];
    __shared__ uint32_t Ws[128 * LDPAD];

    const int tid  = threadIdx.x;
    const int lane = tid & 31;
    const int warp = tid >> 5;
    const int wm   = warp & 3;        // 0..3  -> m offset wm*32
    const int wn   = warp >> 2;       // 0..1  -> n offset wn*64
    const int gid  = lane >> 2;       // 0..7
    const int tig  = lane & 3;        // 0..3
    const int m0   = blockIdx.x * 128;
    const int n0   = blockIdx.y * 128;

    // loader coords: 1024 float4 slots per tile, 4 per thread
    const int lrow = tid >> 3;        // 0..31 (base row, +32 per l)
    const int lkq  = tid & 7;         // 0..7 (float4 within 32-float row)

    float acc[2][8][4];
#pragma unroll
    for (int i = 0; i < 2; i++)
#pragma unroll
        for (int j = 0; j < 8; j++)
#pragma unroll
            for (int q = 0; q < 4; q++) acc[i][j][q] = 0.f;

    const int nt = K / 32;
    for (int kt = 0; kt < nt; kt++) {
        const int kbase = kt * 32;
        // global loads first (overlap with previous compute before sync)
        float4 av[4], wv[4];
#pragma unroll
        for (int l = 0; l < 4; l++) {
            int row = lrow + l * 32;
            av[l] = (m0 + row < M)
                  ? *(const float4*)(A + (size_t)(m0 + row) * K + kbase + lkq * 4)
                  : make_float4(0.f, 0.f, 0.f, 0.f);
            wv[l] = *(const float4*)(W + (size_t)(n0 + row) * K + kbase + lkq * 4);
        }
        if (kt > 0) __syncthreads();
#pragma unroll
        for (int l = 0; l < 4; l++) {
            int row = lrow + l * 32;
            uint4 ua = make_uint4(f2tf32(av[l].x), f2tf32(av[l].y),
                                  f2tf32(av[l].z), f2tf32(av[l].w));
            uint4 uw = make_uint4(f2tf32(wv[l].x), f2tf32(wv[l].y),
                                  f2tf32(wv[l].z), f2tf32(wv[l].w));
            *(uint4*)&As[row * LDPAD + lkq * 4] = ua;
            *(uint4*)&Ws[row * LDPAD + lkq * 4] = uw;
        }
        __syncthreads();

#pragma unroll
        for (int ks = 0; ks < 4; ks++) {
            const int k8 = ks * 8;
            uint32_t af[2][4];
#pragma unroll
            for (int mt = 0; mt < 2; mt++) {
                int rbase = wm * 32 + mt * 16;
                af[mt][0] = As[(rbase + gid) * LDPAD + k8 + tig];
                af[mt][1] = As[(rbase + gid + 8) * LDPAD + k8 + tig];
                af[mt][2] = As[(rbase + gid) * LDPAD + k8 + tig + 4];
                af[mt][3] = As[(rbase + gid + 8) * LDPAD + k8 + tig + 4];
            }
            uint32_t bf[8][2];
#pragma unroll
            for (int ntl = 0; ntl < 8; ntl++) {
                int col = wn * 64 + ntl * 8 + gid;
                bf[ntl][0] = Ws[col * LDPAD + k8 + tig];
                bf[ntl][1] = Ws[col * LDPAD + k8 + tig + 4];
            }
#pragma unroll
            for (int mt = 0; mt < 2; mt++)
#pragma unroll
                for (int ntl = 0; ntl < 8; ntl++)
                    mma_tf32(acc[mt][ntl], af[mt], bf[ntl]);
        }
    }

    // epilogue: c0/c1 -> (row, col..col+1), c2/c3 -> (row+8, ...)
#pragma unroll
    for (int mt = 0; mt < 2; mt++) {
        int row0 = m0 + wm * 32 + mt * 16 + gid;
        int row1 = row0 + 8;
#pragma unroll
        for (int ntl = 0; ntl < 8; ntl++) {
            int col = n0 + wn * 64 + ntl * 8 + tig * 2;
            float bx = 0.f, by = 0.f;
            if (bias) { bx = bias[col]; by = bias[col + 1]; }
            float2 v0 = make_float2(acc[mt][ntl][0] + bx, acc[mt][ntl][1] + by);
            float2 v1 = make_float2(acc[mt][ntl][2] + bx, acc[mt][ntl][3] + by);
            if (doRelu) {
                v0.x = fmaxf(v0.x, 0.f); v0.y = fmaxf(v0.y, 0.f);
                v1.x = fmaxf(v1.x, 0.f); v1.y = fmaxf(v1.y, 0.f);
            }
            if (row0 < M) *(float2*)(C + (size_t)row0 * Nout + col) = v0;
            if (row1 < M) *(float2*)(C + (size_t)row1 * Nout + col) = v1;
        }
    }
}

// ---------------- LayerNorm (+ bias b2): one warp per row --------------------
__global__ void ln_kernel(const float* __restrict__ agg2,
                          const float* __restrict__ b2,
                          const float* __restrict__ gamma,
                          const float* __restrict__ beta,
                          float* __restrict__ out, int n) {
    int row  = (blockIdx.x * blockDim.x + threadIdx.x) >> 5;
    int lane = threadIdx.x & 31;
    if (row >= n) return;

    float4 v  = *(const float4*)(agg2 + (size_t)row * DIN + lane * 4);
    float4 bb = *(const float4*)(b2 + lane * 4);
    v.x += bb.x; v.y += bb.y; v.z += bb.z; v.w += bb.w;

    float s = v.x + v.y + v.z + v.w;
#pragma unroll
    for (int o = 16; o > 0; o >>= 1) s += __shfl_xor_sync(0xFFFFFFFFu, s, o);
    float mu = s * (1.0f / DIN);

    float dx = v.x - mu, dy = v.y - mu, dz = v.z - mu, dw = v.w - mu;
    float q = dx * dx + dy * dy + dz * dz + dw * dw;
#pragma unroll
    for (int o = 16; o > 0; o >>= 1) q += __shfl_xor_sync(0xFFFFFFFFu, q, o);
    float rstd = rsqrtf(q * (1.0f / DIN) + 1e-5f);

    float4 g  = *(const float4*)(gamma + lane * 4);
    float4 bt = *(const float4*)(beta + lane * 4);
    float4 o4;
    o4.x = dx * rstd * g.x + bt.x;
    o4.y = dy * rstd * g.y + bt.y;
    o4.z = dz * rstd * g.z + bt.z;
    o4.w = dw * rstd * g.w + bt.w;
    *(float4*)(out + (size_t)row * DIN + lane * 4) = o4;
}

// -----------------------------------------------------------------------------
extern "C" void kernel_launch(void* const* d_in, const int* in_sizes, int n_in,
                              void* d_out, int out_size) {
    const float* x     = (const float*)d_in[0];
    const void*  ei    = d_in[1];                 // int32 or int64, sniffed
    const float* ew    = (const float*)d_in[2];
    const float* W1    = (const float*)d_in[3];
    const float* b1    = (const float*)d_in[4];
    const float* W2    = (const float*)d_in[5];
    const float* b2    = (const float*)d_in[6];
    const float* gamma = (const float*)d_in[7];
    const float* beta  = (const float*)d_in[8];
    float*       out   = (float*)d_out;

    float *dinv, *agg1, *h, *p, *agg2;
    int *src, *dst;
    cudaGetSymbolAddress((void**)&dinv, g_dinv);
    cudaGetSymbolAddress((void**)&agg1, g_agg1);
    cudaGetSymbolAddress((void**)&h,    g_h);
    cudaGetSymbolAddress((void**)&p,    g_p);
    cudaGetSymbolAddress((void**)&agg2, g_agg2);
    cudaGetSymbolAddress((void**)&src,  g_src);
    cudaGetSymbolAddress((void**)&dst,  g_dst);

    const int n = NN, e = EE;

    // 0. sniff dtype; zero degree buffer
    detect_idx_kernel<<<1, 128>>>((const int*)ei);
    cudaMemsetAsync(dinv, 0, n * sizeof(float));

    // 1. convert indices + accumulate weighted in-degree (fused)
    convert_deg_kernel<<<(e + 255) / 256, 256>>>(ei, ew, src, dst, dinv, e);
    dinv_kernel<<<(n + 255) / 256, 256>>>(dinv, n);

    // 2. agg1 = A_norm @ x  (self-loop pass doubles as zero-init)
    selfloop_init_kernel<<<(n * DIN + 255) / 256, 256>>>(x, dinv, agg1, n * DIN);
    edge_scatter_kernel<<<(e * 32 + 255) / 256, 256>>>(src, dst, ew, dinv, x, agg1, e);

    // 3. h = relu(agg1 @ W1^T + b1)   [N x 256]
    {
        dim3 grid((n + 127) / 128, DH / 128);
        gemm_tf32_kernel<<<grid, 256>>>(agg1, W1, b1, h, n, DIN, DH, 1);
    }

    // 4. p = h @ W2^T  [N x 128], bias deferred to LN
    {
        dim3 grid((n + 127) / 128, DIN / 128);
        gemm_tf32_kernel<<<grid, 256>>>(h, W2, nullptr, p, n, DH, DIN, 0);
    }

    // 5. agg2 = A_norm @ p
    selfloop_init_kernel<<<(n * DIN + 255) / 256, 256>>>(p, dinv, agg2, n * DIN);
    edge_scatter_kernel<<<(e * 32 + 255) / 256, 256>>>(src, dst, ew, dinv, p, agg2, e);

    // 6. out = LN(agg2 + b2) * gamma + beta
    ln_kernel<<<(n * 32 + 255) / 256, 256>>>(agg2, b2, gamma, beta, out, n);
}